// round 14
// baseline (speedup 1.0000x reference)
#include <cuda_runtime.h>
#include <cuda_bf16.h>
#include <cstdint>
#include <cstddef>

#define BD 2048
#define MD 512
#define AD 2048
#define SD 6144
#define NB 64
#define CHOL_P 64  // persistent Cholesky grid (all co-resident)

// smem stage layout: rows padded to 80B (32 bf16 + 16B pad) -> conflict-free lds
#define ROWB 80
#define OAL 10240
#define OBH 20480
#define OBL 30720
#define SSTG 40960
#define DSMEM_TOTAL (2 * SSTG)

__device__ float g_G[AD * AD];
__device__ float g_linv[NB * NB];
__device__ float g_dU[AD];
__device__ float g_x0[BD * AD];
__device__ float g_u[BD * SD];
__device__ unsigned g_mm[2];
__device__ unsigned g_sync;
__device__ __align__(16) __nv_bfloat16 g_phih[SD * AD], g_phil[SD * AD];
__device__ __align__(16) __nv_bfloat16 g_phiTh[AD * SD], g_phiTl[AD * SD];
__device__ __align__(16) __nv_bfloat16 g_aTh[AD * MD], g_aTl[AD * MD];
__device__ __align__(16) __nv_bfloat16 g_yh[BD * MD], g_yl[BD * MD];
__device__ __align__(16) __nv_bfloat16 g_wh[BD * SD], g_wl[BD * SD];
__device__ __align__(16) __nv_bfloat16 g_xhh[BD * AD], g_xhl[BD * AD];

__device__ __forceinline__ unsigned f2o(float f) {
    unsigned b = __float_as_uint(f);
    return (b & 0x80000000u) ? ~b : (b | 0x80000000u);
}
__device__ __forceinline__ float o2f(unsigned u) {
    unsigned b = (u & 0x80000000u) ? (u ^ 0x80000000u) : ~u;
    return __uint_as_float(b);
}
__device__ __forceinline__ void split_bf(float x, __nv_bfloat16& h, __nv_bfloat16& l) {
    __nv_bfloat16 hb = __float2bfloat16(x);
    h = hb;
    l = __float2bfloat16(x - __bfloat162float(hb));
}
__device__ __forceinline__ uint32_t s2u(const void* p) {
    uint32_t a;
    asm("{ .reg .u64 t; cvta.to.shared.u64 t, %1; cvt.u32.u64 %0, t; }" : "=r"(a) : "l"(p));
    return a;
}
__device__ __forceinline__ uint32_t lds32(uint32_t a) {
    uint32_t v;
    asm volatile("ld.shared.b32 %0, [%1];" : "=r"(v) : "r"(a));
    return v;
}
__device__ __forceinline__ void cp16(uint32_t d, const void* s) {
    asm volatile("cp.async.cg.shared.global [%0], [%1], 16;" ::"r"(d), "l"(s));
}
__device__ __forceinline__ void mma16816(float* c, const uint32_t* a, uint32_t b0, uint32_t b1) {
    asm volatile(
        "mma.sync.aligned.m16n8k16.row.col.f32.bf16.bf16.f32 "
        "{%0,%1,%2,%3}, {%4,%5,%6,%7}, {%8,%9}, {%0,%1,%2,%3};"
        : "+f"(c[0]), "+f"(c[1]), "+f"(c[2]), "+f"(c[3])
        : "r"(a[0]), "r"(a[1]), "r"(a[2]), "r"(a[3]), "r"(b0), "r"(b1));
}

__global__ void mm_init_k() {
    g_mm[0] = 0xFFFFFFFFu;
    g_mm[1] = 0u;
}
__global__ void zero_sync_k() { g_sync = 0u; }

__global__ void mm_reduce_k(const float* __restrict__ x, int n) {
    unsigned mn = 0xFFFFFFFFu, mx = 0u;
    for (int i = blockIdx.x * blockDim.x + threadIdx.x; i < n; i += gridDim.x * blockDim.x) {
        unsigned o = f2o(x[i]);
        mn = min(mn, o);
        mx = max(mx, o);
    }
    __shared__ unsigned smn[256], smx[256];
    smn[threadIdx.x] = mn;
    smx[threadIdx.x] = mx;
    __syncthreads();
    for (int s = 128; s > 0; s >>= 1) {
        if (threadIdx.x < s) {
            smn[threadIdx.x] = min(smn[threadIdx.x], smn[threadIdx.x + s]);
            smx[threadIdx.x] = max(smx[threadIdx.x], smx[threadIdx.x + s]);
        }
        __syncthreads();
    }
    if (threadIdx.x == 0) {
        atomicMin(&g_mm[0], smn[0]);
        atomicMax(&g_mm[1], smx[0]);
    }
}

__global__ void split_k(const float* __restrict__ s, __nv_bfloat16* __restrict__ h,
                        __nv_bfloat16* __restrict__ l, int n) {
    int i = blockIdx.x * 256 + threadIdx.x;
    if (i < n) {
        __nv_bfloat16 hh, ll;
        split_bf(s[i], hh, ll);
        h[i] = hh;
        l[i] = ll;
    }
}

// out[c*R + r] = split(src[r*Cc + c])
__global__ void tsplit_k(const float* __restrict__ src, int R, int Cc,
                         __nv_bfloat16* __restrict__ th, __nv_bfloat16* __restrict__ tl) {
    __shared__ float t[32][33];
    int bc = blockIdx.x * 32, br = blockIdx.y * 32;
    int x = threadIdx.x, y = threadIdx.y;
#pragma unroll
    for (int dy = 0; dy < 32; dy += 8) t[y + dy][x] = src[(size_t)(br + y + dy) * Cc + bc + x];
    __syncthreads();
#pragma unroll
    for (int dy = 0; dy < 32; dy += 8) {
        size_t o = (size_t)(bc + y + dy) * R + br + x;
        __nv_bfloat16 h, l;
        split_bf(t[x][y + dy], h, l);
        th[o] = h;
        tl[o] = l;
    }
}

// ---------------- persistent fused Cholesky: 1 launch, 32 rounds ----------------
// grid = CHOL_P blocks of 256 threads, all co-resident. Phases separated by a
// generation-counted global spin barrier.
__global__ __launch_bounds__(256) void chol_all_k(float* __restrict__ G,
                                                  float* __restrict__ linv,
                                                  float* __restrict__ dU) {
    __shared__ float pool[2 * NB * (NB + 1)];  // 8320 floats, reused per phase
    int tid = threadIdx.x;
    int bid = blockIdx.x;
    unsigned gen = 0;

#define GBAR()                                                           \
    do {                                                                 \
        __syncthreads();                                                 \
        if (tid == 0) {                                                  \
            __threadfence();                                             \
            atomicAdd(&g_sync, 1u);                                      \
            unsigned tgt = (++gen) * (unsigned)CHOL_P;                   \
            while (*((volatile unsigned*)&g_sync) < tgt) {}              \
            __threadfence();                                             \
        }                                                                \
        __syncthreads();                                                 \
    } while (0)

    for (int kb = 0; kb < AD / NB; kb++) {
        int k0 = kb * NB;
        int nrem = AD - k0 - NB;

        // ---- Phase A: diagonal block factor + inv(L11), block 0 only ----
        if (bid == 0) {
            float(*s)[NB + 1] = (float(*)[NB + 1])pool;
            float(*xs)[NB + 1] = (float(*)[NB + 1])(pool + NB * (NB + 1));
            int row = tid & 63, seg = tid >> 6;
#pragma unroll
            for (int j = 0; j < 16; j++) {
                int c = seg * 16 + j;
                s[row][c] = G[(size_t)(k0 + row) * AD + k0 + c];
            }
            __syncthreads();
            for (int j = 0; j < NB; j++) {
                float ajj = s[j][j];
                __syncthreads();
                float d = sqrtf(ajj);
                if (seg == 0 && row >= j) {
                    if (row == j) {
                        s[j][j] = d;
                        dU[k0 + j] = 1.0f / (d * d);
                    } else {
                        s[row][j] = s[row][j] / d;
                    }
                }
                __syncthreads();
                if (row > j) {
                    float lj = s[row][j];
                    for (int p = j + 1 + seg; p <= row; p += 4) s[row][p] -= lj * s[p][j];
                }
                __syncthreads();
            }
            if (seg == 0) {
                int c = row;
                for (int r = 0; r < c; r++) xs[r][c] = 0.0f;
                xs[c][c] = 1.0f / s[c][c];
                for (int r = c + 1; r < NB; r++) {
                    float acc = 0.0f;
                    for (int p = c; p < r; p++) acc += s[r][p] * xs[p][c];
                    xs[r][c] = -acc / s[r][r];
                }
            }
            __syncthreads();
            for (int i = tid; i < NB * NB; i += 256) linv[i] = xs[i >> 6][i & 63];
        }
        GBAR();

        // ---- Phase B: panel L21 = A21 * Linv^T (32-row slices) ----
        if (nrem > 0) {
            int npan = nrem / 32;
            for (int sl = bid; sl < npan; sl += CHOL_P) {
                float(*li)[NB + 1] = (float(*)[NB + 1])pool;
                float(*ar)[NB] = (float(*)[NB])(pool + NB * (NB + 1));
                for (int i = tid; i < NB * NB; i += 256) li[i >> 6][i & 63] = linv[i];
                int row0 = k0 + NB + sl * 32;
                for (int i = tid; i < 32 * NB; i += 256) {
                    int r = i >> 6, p = i & 63;
                    ar[r][p] = G[(size_t)(row0 + r) * AD + k0 + p];
                }
                __syncthreads();
                int j = tid & 63;
                for (int r = tid >> 6; r < 32; r += 4) {
                    float acc = 0.0f;
#pragma unroll
                    for (int p = 0; p < NB; p++) acc += ar[r][p] * li[j][p];
                    G[(size_t)(row0 + r) * AD + k0 + j] = acc;
                }
                __syncthreads();  // protect smem before next slice
            }
        }
        GBAR();

        // ---- Phase C: trailing update C -= P P^T (128x128 tiles) ----
        if (nrem > 0) {
            const float* Pp = G + (size_t)(k0 + NB) * AD + k0;
            float* Cc = G + (size_t)(k0 + NB) * AD + (k0 + NB);
            int nbx = (nrem + 127) / 128;
            float(*As)[128] = (float(*)[128])pool;
            float(*Bs)[128] = (float(*)[128])(pool + 16 * 128);
            for (int idx = bid; idx < nbx * nbx; idx += CHOL_P) {
                int bm0 = (idx / nbx) * 128, bn0 = (idx % nbx) * 128;
                int tx = tid & 15, ty = tid >> 4;
                float acc[8][8];
#pragma unroll
                for (int i = 0; i < 8; i++)
#pragma unroll
                    for (int j = 0; j < 8; j++) acc[i][j] = 0.0f;
                for (int kk = 0; kk < NB; kk += 16) {
#pragma unroll
                    for (int L = 0; L < 2; L++) {
                        int ii = tid + L * 256;
                        int r = ii >> 2, fk = (ii & 3) << 2;
                        float4 v = make_float4(0.f, 0.f, 0.f, 0.f);
                        if ((bm0 + r) < nrem)
                            v = *(const float4*)(Pp + (size_t)(bm0 + r) * AD + kk + fk);
                        As[fk + 0][r] = v.x;
                        As[fk + 1][r] = v.y;
                        As[fk + 2][r] = v.z;
                        As[fk + 3][r] = v.w;
                    }
#pragma unroll
                    for (int L = 0; L < 2; L++) {
                        int ii = tid + L * 256;
                        int r = ii >> 2, fk = (ii & 3) << 2;
                        float4 v = make_float4(0.f, 0.f, 0.f, 0.f);
                        if ((bn0 + r) < nrem)
                            v = *(const float4*)(Pp + (size_t)(bn0 + r) * AD + kk + fk);
                        Bs[fk + 0][r] = v.x;
                        Bs[fk + 1][r] = v.y;
                        Bs[fk + 2][r] = v.z;
                        Bs[fk + 3][r] = v.w;
                    }
                    __syncthreads();
#pragma unroll
                    for (int k = 0; k < 16; k++) {
                        float arf[8], brf[8];
#pragma unroll
                        for (int i = 0; i < 8; i++) arf[i] = As[k][ty * 8 + i];
#pragma unroll
                        for (int j = 0; j < 8; j++) brf[j] = Bs[k][tx * 8 + j];
#pragma unroll
                        for (int i = 0; i < 8; i++)
#pragma unroll
                            for (int j = 0; j < 8; j++) acc[i][j] += arf[i] * brf[j];
                    }
                    __syncthreads();
                }
#pragma unroll
                for (int i = 0; i < 8; i++) {
                    int row = bm0 + ty * 8 + i;
                    if (row >= nrem) continue;
#pragma unroll
                    for (int j = 0; j < 8; j++) {
                        int col = bn0 + tx * 8 + j;
                        if (col >= nrem) continue;
                        Cc[(size_t)row * AD + col] -= acc[i][j];
                    }
                }
            }
        }
        GBAR();
    }
#undef GBAR
}

// ---------------- warp-MMA bf16x3 GEMM (128x128 CTA, 2 CTAs/SM), fused epilogues --------
enum { EP_G_STORE = 0, EP_G_ADD, EP_X0, EP_XHAT, EP_XHAT_CLIP, EP_ADMM, EP_ADMM_U0 };

template <int EPI>
__device__ __forceinline__ void ep2(float2 v, int row, int col, int N, float* C,
                                    const float* x0p, const float* dUp, float* up,
                                    __nv_bfloat16* oh, __nv_bfloat16* ol, float* outp,
                                    float mnv, float mxv) {
    size_t o = (size_t)row * N + col;
    if (EPI == EP_G_STORE) {
        *(float2*)(C + o) = v;
    } else if (EPI == EP_G_ADD) {
        float2 g = *(float2*)(C + o);
        g.x += v.x;
        g.y += v.y;
        *(float2*)(C + o) = g;
    } else if (EPI == EP_X0) {
        *(float2*)(C + o) = v;
        float2 d = *(const float2*)(dUp + col);
        __nv_bfloat162 hh, ll;
        split_bf(d.x * v.x, hh.x, ll.x);
        split_bf(d.y * v.y, hh.y, ll.y);
        *(__nv_bfloat162*)(oh + o) = hh;
        *(__nv_bfloat162*)(ol + o) = ll;
    } else if (EPI == EP_XHAT) {
        float2 x0v = *(const float2*)(x0p + o);
        float2 d = *(const float2*)(dUp + col);
        __nv_bfloat162 hh, ll;
        split_bf(d.x * (x0v.x + v.x), hh.x, ll.x);
        split_bf(d.y * (x0v.y + v.y), hh.y, ll.y);
        *(__nv_bfloat162*)(oh + o) = hh;
        *(__nv_bfloat162*)(ol + o) = ll;
    } else if (EPI == EP_XHAT_CLIP) {
        float2 x0v = *(const float2*)(x0p + o);
        float2 d = *(const float2*)(dUp + col);
        float2 t;
        t.x = fminf(fmaxf(d.x * (x0v.x + v.x), mnv), mxv);
        t.y = fminf(fmaxf(d.y * (x0v.y + v.y), mnv), mxv);
        *(float2*)(outp + o) = t;
    } else {
        float2 uo = make_float2(0.f, 0.f);
        if (EPI == EP_ADMM) uo = *(float2*)(up + o);
        __nv_bfloat162 hh, ll;
        float2 un;
#pragma unroll
        for (int e = 0; e < 2; e++) {
            float fxu = (e ? v.y : v.x) + (e ? uo.y : uo.x);
            float sa = fabsf(fxu) - 0.1f;  // LAMDA / RHO
            float z = sa > 0.0f ? copysignf(sa, fxu) : 0.0f;
            float u2 = (e ? uo.y : uo.x) + fxu - z;
            if (e) un.y = u2; else un.x = u2;
            __nv_bfloat16 h, l;
            split_bf(z - u2, h, l);
            if (e) { hh.y = h; ll.y = l; } else { hh.x = h; ll.x = l; }
        }
        *(float2*)(up + o) = un;
        *(__nv_bfloat162*)(oh + o) = hh;
        *(__nv_bfloat162*)(ol + o) = ll;
    }
}

template <int EPI>
__global__ __launch_bounds__(256, 2) void tgemm_k(
    const __nv_bfloat16* __restrict__ Ah, const __nv_bfloat16* __restrict__ Al, int lda,
    const __nv_bfloat16* __restrict__ Bh, const __nv_bfloat16* __restrict__ Bl, int ldb,
    int K, int N, float* __restrict__ C, const float* __restrict__ x0p,
    const float* __restrict__ dUp, float* __restrict__ up, __nv_bfloat16* __restrict__ oh,
    __nv_bfloat16* __restrict__ ol, float* __restrict__ outp) {
    extern __shared__ char ds[];
    uint32_t sb = s2u(ds);
    int tid = threadIdx.x, wid = tid >> 5, lane = tid & 31;
    int q = lane >> 2, t = lane & 3;
    int wm = wid >> 1, wn = wid & 1;
    int m0 = blockIdx.y * 128, n0 = blockIdx.x * 128;

    float acc[2][8][4];
#pragma unroll
    for (int mi = 0; mi < 2; mi++)
#pragma unroll
        for (int nj = 0; nj < 8; nj++)
#pragma unroll
            for (int e = 0; e < 4; e++) acc[mi][nj][e] = 0.0f;

    int lr = tid >> 2, lc = tid & 3;  // load row (0..63), chunk (0..3)
    int nK = K / 32;

    // ---- issue stage 0 ----
    {
        uint32_t st = sb;
        int gc = lc * 8;
#pragma unroll
        for (int i = 0; i < 2; i++) {
            int r = lr + i * 64;
            uint32_t dso = st + r * ROWB + lc * 16;
            cp16(dso, Ah + (size_t)(m0 + r) * lda + gc);
            cp16(dso + OAL, Al + (size_t)(m0 + r) * lda + gc);
            cp16(dso + OBH, Bh + (size_t)(n0 + r) * ldb + gc);
            cp16(dso + OBL, Bl + (size_t)(n0 + r) * ldb + gc);
        }
        asm volatile("cp.async.commit_group;" ::: "memory");
    }

    for (int kb = 0; kb < nK; kb++) {
        int buf = kb & 1;
        if (kb + 1 < nK) {
            uint32_t st = sb + (buf ^ 1) * SSTG;
            int gc = (kb + 1) * 32 + lc * 8;
#pragma unroll
            for (int i = 0; i < 2; i++) {
                int r = lr + i * 64;
                uint32_t dso = st + r * ROWB + lc * 16;
                cp16(dso, Ah + (size_t)(m0 + r) * lda + gc);
                cp16(dso + OAL, Al + (size_t)(m0 + r) * lda + gc);
                cp16(dso + OBH, Bh + (size_t)(n0 + r) * ldb + gc);
                cp16(dso + OBL, Bl + (size_t)(n0 + r) * ldb + gc);
            }
            asm volatile("cp.async.commit_group;" ::: "memory");
            asm volatile("cp.async.wait_group 1;" ::: "memory");
        } else {
            asm volatile("cp.async.wait_group 0;" ::: "memory");
        }
        __syncthreads();

        uint32_t st = sb + buf * SSTG;
        uint32_t abase = st + (wm * 32 + q) * ROWB + t * 4;
        uint32_t bbase = st + OBH + (wn * 64 + q) * ROWB + t * 4;
#pragma unroll
        for (int s = 0; s < 2; s++) {
            uint32_t ko = s * 32;
            uint32_t ah[2][4], al[2][4];
#pragma unroll
            for (int mi = 0; mi < 2; mi++) {
                uint32_t ro = abase + mi * (16 * ROWB) + ko;
                ah[mi][0] = lds32(ro);
                ah[mi][1] = lds32(ro + 8 * ROWB);
                ah[mi][2] = lds32(ro + 16);
                ah[mi][3] = lds32(ro + 8 * ROWB + 16);
                al[mi][0] = lds32(ro + OAL);
                al[mi][1] = lds32(ro + OAL + 8 * ROWB);
                al[mi][2] = lds32(ro + OAL + 16);
                al[mi][3] = lds32(ro + OAL + 8 * ROWB + 16);
            }
#pragma unroll
            for (int njp = 0; njp < 4; njp++) {
                int nj0 = njp * 2, nj1 = nj0 + 1;
                uint32_t bo0 = bbase + nj0 * (8 * ROWB) + ko;
                uint32_t bo1 = bbase + nj1 * (8 * ROWB) + ko;
                uint32_t bh[4], bl[4];
                bh[0] = lds32(bo0);
                bh[1] = lds32(bo0 + 16);
                bh[2] = lds32(bo1);
                bh[3] = lds32(bo1 + 16);
                bl[0] = lds32(bo0 + 10240);
                bl[1] = lds32(bo0 + 10240 + 16);
                bl[2] = lds32(bo1 + 10240);
                bl[3] = lds32(bo1 + 10240 + 16);
                // term-major across the pair: acc reuse distance 4
                mma16816(acc[0][nj0], ah[0], bh[0], bh[1]);
                mma16816(acc[1][nj0], ah[1], bh[0], bh[1]);
                mma16816(acc[0][nj1], ah[0], bh[2], bh[3]);
                mma16816(acc[1][nj1], ah[1], bh[2], bh[3]);
                mma16816(acc[0][nj0], ah[0], bl[0], bl[1]);
                mma16816(acc[1][nj0], ah[1], bl[0], bl[1]);
                mma16816(acc[0][nj1], ah[0], bl[2], bl[3]);
                mma16816(acc[1][nj1], ah[1], bl[2], bl[3]);
                mma16816(acc[0][nj0], al[0], bh[0], bh[1]);
                mma16816(acc[1][nj0], al[1], bh[0], bh[1]);
                mma16816(acc[0][nj1], al[0], bh[2], bh[3]);
                mma16816(acc[1][nj1], al[1], bh[2], bh[3]);
            }
        }
        __syncthreads();
    }

    float mnv = 0.f, mxv = 0.f;
    if (EPI == EP_XHAT_CLIP) {
        mnv = o2f(g_mm[0]);
        mxv = o2f(g_mm[1]);
    }
#pragma unroll
    for (int mi = 0; mi < 2; mi++)
#pragma unroll
        for (int nj = 0; nj < 8; nj++) {
            int row = m0 + wm * 32 + mi * 16 + q;
            int col = n0 + wn * 64 + nj * 8 + 2 * t;
            ep2<EPI>(make_float2(acc[mi][nj][0], acc[mi][nj][1]), row, col, N, C, x0p, dUp, up,
                     oh, ol, outp, mnv, mxv);
            ep2<EPI>(make_float2(acc[mi][nj][2], acc[mi][nj][3]), row + 8, col, N, C, x0p, dUp,
                     up, oh, ol, outp, mnv, mxv);
        }
}

extern "C" void kernel_launch(void* const* d_in, const int* in_sizes, int n_in,
                              void* d_out, int out_size) {
    const float* y = (const float*)d_in[0];
    const float* x = (const float*)d_in[1];
    const float* a = (const float*)d_in[2];
    const float* phi = (const float*)d_in[3];
    float* out = (float*)d_out;

    float *G, *linv, *dU, *x0, *u;
    __nv_bfloat16 *phih, *phil, *phiTh, *phiTl, *aTh, *aTl, *yh, *yl, *wh, *wl, *xhh, *xhl;
    cudaGetSymbolAddress((void**)&G, g_G);
    cudaGetSymbolAddress((void**)&linv, g_linv);
    cudaGetSymbolAddress((void**)&dU, g_dU);
    cudaGetSymbolAddress((void**)&x0, g_x0);
    cudaGetSymbolAddress((void**)&u, g_u);
    cudaGetSymbolAddress((void**)&phih, g_phih);
    cudaGetSymbolAddress((void**)&phil, g_phil);
    cudaGetSymbolAddress((void**)&phiTh, g_phiTh);
    cudaGetSymbolAddress((void**)&phiTl, g_phiTl);
    cudaGetSymbolAddress((void**)&aTh, g_aTh);
    cudaGetSymbolAddress((void**)&aTl, g_aTl);
    cudaGetSymbolAddress((void**)&yh, g_yh);
    cudaGetSymbolAddress((void**)&yl, g_yl);
    cudaGetSymbolAddress((void**)&wh, g_wh);
    cudaGetSymbolAddress((void**)&wl, g_wl);
    cudaGetSymbolAddress((void**)&xhh, g_xhh);
    cudaGetSymbolAddress((void**)&xhl, g_xhl);

    cudaFuncSetAttribute(tgemm_k<EP_G_STORE>, cudaFuncAttributeMaxDynamicSharedMemorySize, DSMEM_TOTAL);
    cudaFuncSetAttribute(tgemm_k<EP_G_ADD>, cudaFuncAttributeMaxDynamicSharedMemorySize, DSMEM_TOTAL);
    cudaFuncSetAttribute(tgemm_k<EP_X0>, cudaFuncAttributeMaxDynamicSharedMemorySize, DSMEM_TOTAL);
    cudaFuncSetAttribute(tgemm_k<EP_XHAT>, cudaFuncAttributeMaxDynamicSharedMemorySize, DSMEM_TOTAL);
    cudaFuncSetAttribute(tgemm_k<EP_XHAT_CLIP>, cudaFuncAttributeMaxDynamicSharedMemorySize, DSMEM_TOTAL);
    cudaFuncSetAttribute(tgemm_k<EP_ADMM>, cudaFuncAttributeMaxDynamicSharedMemorySize, DSMEM_TOTAL);
    cudaFuncSetAttribute(tgemm_k<EP_ADMM_U0>, cudaFuncAttributeMaxDynamicSharedMemorySize, DSMEM_TOTAL);

    dim3 blk(256);
    dim3 b32(32, 8);
    dim3 gG(AD / 128, AD / 128);   // (16,16)
    dim3 g1(AD / 128, BD / 128);   // (16,16)
    dim3 g2(SD / 128, BD / 128);   // (48,16)

    // order chosen so ncu's captured launch (index 3) is the big phi^T phi GEMM
    tsplit_k<<<dim3(AD / 32, SD / 32), b32>>>(phi, SD, AD, phiTh, phiTl);   // 0
    tsplit_k<<<dim3(AD / 32, MD / 32), b32>>>(a, MD, AD, aTh, aTl);         // 1
    split_k<<<(SD * AD) / 256, 256>>>(phi, phih, phil, SD * AD);            // 2
    // G = phi^T phi   (index 3 -> profiled)
    tgemm_k<EP_G_STORE><<<gG, blk, DSMEM_TOTAL>>>(phiTh, phiTl, SD, phiTh, phiTl, SD, SD, AD, G,
                                                  nullptr, nullptr, nullptr, nullptr, nullptr, nullptr);
    mm_init_k<<<1, 1>>>();
    mm_reduce_k<<<256, 256>>>(x, BD * AD);
    split_k<<<(BD * MD) / 256, 256>>>(y, yh, yl, BD * MD);
    // G += a^T a
    tgemm_k<EP_G_ADD><<<gG, blk, DSMEM_TOTAL>>>(aTh, aTl, MD, aTh, aTl, MD, MD, AD, G,
                                                nullptr, nullptr, nullptr, nullptr, nullptr, nullptr);

    // fused persistent Cholesky (1 launch replaces 95)
    zero_sync_k<<<1, 1>>>();
    chol_all_k<<<CHOL_P, 256>>>(G, linv, dU);

    // x0 = y@a ; also xh = dU*x0 (iter-1, w=0)
    tgemm_k<EP_X0><<<g1, blk, DSMEM_TOTAL>>>(yh, yl, MD, aTh, aTl, MD, MD, AD, x0,
                                             nullptr, dU, nullptr, xhh, xhl, nullptr);
    // iter 1 second half: u = 0
    tgemm_k<EP_ADMM_U0><<<g2, blk, DSMEM_TOTAL>>>(xhh, xhl, AD, phih, phil, AD, AD, SD, nullptr,
                                                  nullptr, nullptr, u, wh, wl, nullptr);
    for (int it = 2; it <= 9; it++) {
        tgemm_k<EP_XHAT><<<g1, blk, DSMEM_TOTAL>>>(wh, wl, SD, phiTh, phiTl, SD, SD, AD, nullptr,
                                                   x0, dU, nullptr, xhh, xhl, nullptr);
        tgemm_k<EP_ADMM><<<g2, blk, DSMEM_TOTAL>>>(xhh, xhl, AD, phih, phil, AD, AD, SD, nullptr,
                                                   nullptr, nullptr, u, wh, wl, nullptr);
    }
    tgemm_k<EP_XHAT_CLIP><<<g1, blk, DSMEM_TOTAL>>>(wh, wl, SD, phiTh, phiTl, SD, SD, AD, nullptr,
                                                    x0, dU, nullptr, nullptr, nullptr, out);
}

// round 15
// speedup vs baseline: 1.0346x; 1.0346x over previous
#include <cuda_runtime.h>
#include <cuda_bf16.h>
#include <cstdint>
#include <cstddef>

#define BD 2048
#define MD 512
#define AD 2048
#define SD 6144
#define KT 6656  // MD + SD, packed Gram K
#define NB 64

// smem stage layout: rows padded to 80B (32 bf16 + 16B pad) -> conflict-free lds
#define ROWB 80
#define OAL 10240
#define OBH 20480
#define OBL 30720
#define SSTG 40960
#define DSMEM_TOTAL (2 * SSTG)

__device__ float g_G[AD * AD];
__device__ float g_linv[NB * NB];
__device__ float g_dU[AD];
__device__ float g_x0[BD * AD];
__device__ float g_u[BD * SD];
__device__ unsigned g_mm[2];
__device__ __align__(16) __nv_bfloat16 g_gTh[AD * KT], g_gTl[AD * KT];  // [aT | phiT] K-major
__device__ __align__(16) __nv_bfloat16 g_phih[SD * AD], g_phil[SD * AD];
__device__ __align__(16) __nv_bfloat16 g_yh[BD * MD], g_yl[BD * MD];
__device__ __align__(16) __nv_bfloat16 g_wh[BD * SD], g_wl[BD * SD];
__device__ __align__(16) __nv_bfloat16 g_xhh[BD * AD], g_xhl[BD * AD];

__device__ __forceinline__ unsigned f2o(float f) {
    unsigned b = __float_as_uint(f);
    return (b & 0x80000000u) ? ~b : (b | 0x80000000u);
}
__device__ __forceinline__ float o2f(unsigned u) {
    unsigned b = (u & 0x80000000u) ? (u ^ 0x80000000u) : ~u;
    return __uint_as_float(b);
}
__device__ __forceinline__ void split_bf(float x, __nv_bfloat16& h, __nv_bfloat16& l) {
    __nv_bfloat16 hb = __float2bfloat16(x);
    h = hb;
    l = __float2bfloat16(x - __bfloat162float(hb));
}
__device__ __forceinline__ uint32_t s2u(const void* p) {
    uint32_t a;
    asm("{ .reg .u64 t; cvta.to.shared.u64 t, %1; cvt.u32.u64 %0, t; }" : "=r"(a) : "l"(p));
    return a;
}
__device__ __forceinline__ uint32_t lds32(uint32_t a) {
    uint32_t v;
    asm volatile("ld.shared.b32 %0, [%1];" : "=r"(v) : "r"(a));
    return v;
}
__device__ __forceinline__ void cp16(uint32_t d, const void* s) {
    asm volatile("cp.async.cg.shared.global [%0], [%1], 16;" ::"r"(d), "l"(s));
}
__device__ __forceinline__ void mma16816(float* c, const uint32_t* a, uint32_t b0, uint32_t b1) {
    asm volatile(
        "mma.sync.aligned.m16n8k16.row.col.f32.bf16.bf16.f32 "
        "{%0,%1,%2,%3}, {%4,%5,%6,%7}, {%8,%9}, {%0,%1,%2,%3};"
        : "+f"(c[0]), "+f"(c[1]), "+f"(c[2]), "+f"(c[3])
        : "r"(a[0]), "r"(a[1]), "r"(a[2]), "r"(a[3]), "r"(b0), "r"(b1));
}

__global__ void mm_init_k() {
    g_mm[0] = 0xFFFFFFFFu;
    g_mm[1] = 0u;
}
__global__ void mm_reduce_k(const float* __restrict__ x, int n) {
    unsigned mn = 0xFFFFFFFFu, mx = 0u;
    for (int i = blockIdx.x * blockDim.x + threadIdx.x; i < n; i += gridDim.x * blockDim.x) {
        unsigned o = f2o(x[i]);
        mn = min(mn, o);
        mx = max(mx, o);
    }
    __shared__ unsigned smn[256], smx[256];
    smn[threadIdx.x] = mn;
    smx[threadIdx.x] = mx;
    __syncthreads();
    for (int s = 128; s > 0; s >>= 1) {
        if (threadIdx.x < s) {
            smn[threadIdx.x] = min(smn[threadIdx.x], smn[threadIdx.x + s]);
            smx[threadIdx.x] = max(smx[threadIdx.x], smx[threadIdx.x + s]);
        }
        __syncthreads();
    }
    if (threadIdx.x == 0) {
        atomicMin(&g_mm[0], smn[0]);
        atomicMax(&g_mm[1], smx[0]);
    }
}

__global__ void split_k(const float* __restrict__ s, __nv_bfloat16* __restrict__ h,
                        __nv_bfloat16* __restrict__ l, int n) {
    int i = blockIdx.x * 256 + threadIdx.x;
    if (i < n) {
        __nv_bfloat16 hh, ll;
        split_bf(s[i], hh, ll);
        h[i] = hh;
        l[i] = ll;
    }
}

// transposed split with output row-stride ld: out[c*ld + r] = split(src[r*Cc + c])
__global__ void tsplit_k(const float* __restrict__ src, int R, int Cc, int ld,
                         __nv_bfloat16* __restrict__ th, __nv_bfloat16* __restrict__ tl) {
    __shared__ float t[32][33];
    int bc = blockIdx.x * 32, br = blockIdx.y * 32;
    int x = threadIdx.x, y = threadIdx.y;
#pragma unroll
    for (int dy = 0; dy < 32; dy += 8) t[y + dy][x] = src[(size_t)(br + y + dy) * Cc + bc + x];
    __syncthreads();
#pragma unroll
    for (int dy = 0; dy < 32; dy += 8) {
        size_t o = (size_t)(bc + y + dy) * ld + br + x;
        __nv_bfloat16 h, l;
        split_bf(t[x][y + dy], h, l);
        th[o] = h;
        tl[o] = l;
    }
}

// 256 threads: parallel rank-1 updates (4 lanes per row)
__global__ void chol_diag_k(float* __restrict__ G, float* __restrict__ linv,
                            float* __restrict__ dU, int k0) {
    __shared__ float s[NB][NB + 1];
    __shared__ float xs[NB][NB + 1];
    int tid = threadIdx.x;
    int row = tid & 63, seg = tid >> 6;
#pragma unroll
    for (int j = 0; j < 16; j++) {
        int c = seg * 16 + j;
        s[row][c] = G[(size_t)(k0 + row) * AD + k0 + c];
    }
    __syncthreads();
    for (int j = 0; j < NB; j++) {
        float ajj = s[j][j];
        __syncthreads();
        float d = sqrtf(ajj);
        if (seg == 0 && row >= j) {
            if (row == j) {
                s[j][j] = d;
                dU[k0 + j] = 1.0f / (d * d);
            } else {
                s[row][j] = s[row][j] / d;
            }
        }
        __syncthreads();
        if (row > j) {
            float lj = s[row][j];
            for (int p = j + 1 + seg; p <= row; p += 4) s[row][p] -= lj * s[p][j];
        }
        __syncthreads();
    }
    if (seg == 0) {
        int c = row;
        for (int r = 0; r < c; r++) xs[r][c] = 0.0f;
        xs[c][c] = 1.0f / s[c][c];
        for (int r = c + 1; r < NB; r++) {
            float acc = 0.0f;
            for (int p = c; p < r; p++) acc += s[r][p] * xs[p][c];
            xs[r][c] = -acc / s[r][r];
        }
    }
    __syncthreads();
    for (int i = tid; i < NB * NB; i += 256) linv[i] = xs[i >> 6][i & 63];
}

__global__ void panel_k(float* __restrict__ G, const float* __restrict__ linv, int k0) {
    __shared__ float li[NB][NB + 1];
    __shared__ float ar[32][NB];
    int tid = threadIdx.x;
    for (int i = tid; i < NB * NB; i += 256) li[i >> 6][i & 63] = linv[i];
    int row0 = k0 + NB + blockIdx.x * 32;
    for (int i = tid; i < 32 * NB; i += 256) {
        int r = i >> 6, p = i & 63;
        ar[r][p] = G[(size_t)(row0 + r) * AD + k0 + p];
    }
    __syncthreads();
    int j = tid & 63;
    for (int r = tid >> 6; r < 32; r += 4) {
        float acc = 0.0f;
#pragma unroll
        for (int p = 0; p < NB; p++) acc += ar[r][p] * li[j][p];
        G[(size_t)(row0 + r) * AD + k0 + j] = acc;
    }
}

// trailing update: C(Mr x Mr, ld) -= P(Mr x 64, ld) @ P^T
__global__ __launch_bounds__(256) void syrk_k(const float* __restrict__ P, float* __restrict__ C,
                                              int Mr, int ld) {
    __shared__ float As[16][128];
    __shared__ float Bs[16][128];
    int tid = threadIdx.x;
    int bm0 = blockIdx.y * 128, bn0 = blockIdx.x * 128;
    int tx = tid & 15, ty = tid >> 4;
    float acc[8][8];
#pragma unroll
    for (int i = 0; i < 8; i++)
#pragma unroll
        for (int j = 0; j < 8; j++) acc[i][j] = 0.0f;
    for (int k0 = 0; k0 < 64; k0 += 16) {
#pragma unroll
        for (int L = 0; L < 2; L++) {
            int idx = tid + L * 256;
            int r = idx >> 2, fk = (idx & 3) << 2;
            float4 v = make_float4(0.f, 0.f, 0.f, 0.f);
            if ((bm0 + r) < Mr) v = *(const float4*)(P + (size_t)(bm0 + r) * ld + k0 + fk);
            As[fk + 0][r] = v.x;
            As[fk + 1][r] = v.y;
            As[fk + 2][r] = v.z;
            As[fk + 3][r] = v.w;
        }
#pragma unroll
        for (int L = 0; L < 2; L++) {
            int idx = tid + L * 256;
            int r = idx >> 2, fk = (idx & 3) << 2;
            float4 v = make_float4(0.f, 0.f, 0.f, 0.f);
            if ((bn0 + r) < Mr) v = *(const float4*)(P + (size_t)(bn0 + r) * ld + k0 + fk);
            Bs[fk + 0][r] = v.x;
            Bs[fk + 1][r] = v.y;
            Bs[fk + 2][r] = v.z;
            Bs[fk + 3][r] = v.w;
        }
        __syncthreads();
#pragma unroll
        for (int k = 0; k < 16; k++) {
            float arf[8], brf[8];
#pragma unroll
            for (int i = 0; i < 8; i++) arf[i] = As[k][ty * 8 + i];
#pragma unroll
            for (int j = 0; j < 8; j++) brf[j] = Bs[k][tx * 8 + j];
#pragma unroll
            for (int i = 0; i < 8; i++)
#pragma unroll
                for (int j = 0; j < 8; j++) acc[i][j] += arf[i] * brf[j];
        }
        __syncthreads();
    }
#pragma unroll
    for (int i = 0; i < 8; i++) {
        int row = bm0 + ty * 8 + i;
        if (row >= Mr) continue;
#pragma unroll
        for (int j = 0; j < 8; j++) {
            int col = bn0 + tx * 8 + j;
            if (col >= Mr) continue;
            C[(size_t)row * ld + col] -= acc[i][j];
        }
    }
}

// ---------------- warp-MMA bf16x3 GEMM (128x128 CTA, 2 CTAs/SM), fused epilogues --------
enum { EP_G_STORE = 0, EP_X0, EP_XHAT, EP_XHAT_CLIP, EP_ADMM, EP_ADMM_U0 };

template <int EPI>
__device__ __forceinline__ void ep2(float2 v, int row, int col, int N, float* C,
                                    const float* x0p, const float* dUp, float* up,
                                    __nv_bfloat16* oh, __nv_bfloat16* ol, float* outp,
                                    float mnv, float mxv) {
    size_t o = (size_t)row * N + col;
    if (EPI == EP_G_STORE) {
        *(float2*)(C + o) = v;
    } else if (EPI == EP_X0) {
        *(float2*)(C + o) = v;
        float2 d = *(const float2*)(dUp + col);
        __nv_bfloat162 hh, ll;
        split_bf(d.x * v.x, hh.x, ll.x);
        split_bf(d.y * v.y, hh.y, ll.y);
        *(__nv_bfloat162*)(oh + o) = hh;
        *(__nv_bfloat162*)(ol + o) = ll;
    } else if (EPI == EP_XHAT) {
        float2 x0v = *(const float2*)(x0p + o);
        float2 d = *(const float2*)(dUp + col);
        __nv_bfloat162 hh, ll;
        split_bf(d.x * (x0v.x + v.x), hh.x, ll.x);
        split_bf(d.y * (x0v.y + v.y), hh.y, ll.y);
        *(__nv_bfloat162*)(oh + o) = hh;
        *(__nv_bfloat162*)(ol + o) = ll;
    } else if (EPI == EP_XHAT_CLIP) {
        float2 x0v = *(const float2*)(x0p + o);
        float2 d = *(const float2*)(dUp + col);
        float2 t;
        t.x = fminf(fmaxf(d.x * (x0v.x + v.x), mnv), mxv);
        t.y = fminf(fmaxf(d.y * (x0v.y + v.y), mnv), mxv);
        *(float2*)(outp + o) = t;
    } else {
        float2 uo = make_float2(0.f, 0.f);
        if (EPI == EP_ADMM) uo = *(float2*)(up + o);
        __nv_bfloat162 hh, ll;
        float2 un;
#pragma unroll
        for (int e = 0; e < 2; e++) {
            float fxu = (e ? v.y : v.x) + (e ? uo.y : uo.x);
            float sa = fabsf(fxu) - 0.1f;  // LAMDA / RHO
            float z = sa > 0.0f ? copysignf(sa, fxu) : 0.0f;
            float u2 = (e ? uo.y : uo.x) + fxu - z;
            if (e) un.y = u2; else un.x = u2;
            __nv_bfloat16 h, l;
            split_bf(z - u2, h, l);
            if (e) { hh.y = h; ll.y = l; } else { hh.x = h; ll.x = l; }
        }
        *(float2*)(up + o) = un;
        *(__nv_bfloat162*)(oh + o) = hh;
        *(__nv_bfloat162*)(ol + o) = ll;
    }
}

template <int EPI>
__global__ __launch_bounds__(256, 2) void tgemm_k(
    const __nv_bfloat16* __restrict__ Ah, const __nv_bfloat16* __restrict__ Al, int lda,
    const __nv_bfloat16* __restrict__ Bh, const __nv_bfloat16* __restrict__ Bl, int ldb,
    int K, int N, float* __restrict__ C, const float* __restrict__ x0p,
    const float* __restrict__ dUp, float* __restrict__ up, __nv_bfloat16* __restrict__ oh,
    __nv_bfloat16* __restrict__ ol, float* __restrict__ outp) {
    extern __shared__ char ds[];
    uint32_t sb = s2u(ds);
    int tid = threadIdx.x, wid = tid >> 5, lane = tid & 31;
    int q = lane >> 2, t = lane & 3;
    int wm = wid >> 1, wn = wid & 1;
    int m0 = blockIdx.y * 128, n0 = blockIdx.x * 128;

    float acc[2][8][4];
#pragma unroll
    for (int mi = 0; mi < 2; mi++)
#pragma unroll
        for (int nj = 0; nj < 8; nj++)
#pragma unroll
            for (int e = 0; e < 4; e++) acc[mi][nj][e] = 0.0f;

    int lr = tid >> 2, lc = tid & 3;  // load row (0..63), chunk (0..3)
    int nK = K / 32;

    // ---- issue stage 0 ----
    {
        uint32_t st = sb;
        int gc = lc * 8;
#pragma unroll
        for (int i = 0; i < 2; i++) {
            int r = lr + i * 64;
            uint32_t dso = st + r * ROWB + lc * 16;
            cp16(dso, Ah + (size_t)(m0 + r) * lda + gc);
            cp16(dso + OAL, Al + (size_t)(m0 + r) * lda + gc);
            cp16(dso + OBH, Bh + (size_t)(n0 + r) * ldb + gc);
            cp16(dso + OBL, Bl + (size_t)(n0 + r) * ldb + gc);
        }
        asm volatile("cp.async.commit_group;" ::: "memory");
    }

    for (int kb = 0; kb < nK; kb++) {
        int buf = kb & 1;
        if (kb + 1 < nK) {
            uint32_t st = sb + (buf ^ 1) * SSTG;
            int gc = (kb + 1) * 32 + lc * 8;
#pragma unroll
            for (int i = 0; i < 2; i++) {
                int r = lr + i * 64;
                uint32_t dso = st + r * ROWB + lc * 16;
                cp16(dso, Ah + (size_t)(m0 + r) * lda + gc);
                cp16(dso + OAL, Al + (size_t)(m0 + r) * lda + gc);
                cp16(dso + OBH, Bh + (size_t)(n0 + r) * ldb + gc);
                cp16(dso + OBL, Bl + (size_t)(n0 + r) * ldb + gc);
            }
            asm volatile("cp.async.commit_group;" ::: "memory");
            asm volatile("cp.async.wait_group 1;" ::: "memory");
        } else {
            asm volatile("cp.async.wait_group 0;" ::: "memory");
        }
        __syncthreads();

        uint32_t st = sb + buf * SSTG;
        uint32_t abase = st + (wm * 32 + q) * ROWB + t * 4;
        uint32_t bbase = st + OBH + (wn * 64 + q) * ROWB + t * 4;
#pragma unroll
        for (int s = 0; s < 2; s++) {
            uint32_t ko = s * 32;
            uint32_t ah[2][4], al[2][4];
#pragma unroll
            for (int mi = 0; mi < 2; mi++) {
                uint32_t ro = abase + mi * (16 * ROWB) + ko;
                ah[mi][0] = lds32(ro);
                ah[mi][1] = lds32(ro + 8 * ROWB);
                ah[mi][2] = lds32(ro + 16);
                ah[mi][3] = lds32(ro + 8 * ROWB + 16);
                al[mi][0] = lds32(ro + OAL);
                al[mi][1] = lds32(ro + OAL + 8 * ROWB);
                al[mi][2] = lds32(ro + OAL + 16);
                al[mi][3] = lds32(ro + OAL + 8 * ROWB + 16);
            }
#pragma unroll
            for (int njp = 0; njp < 4; njp++) {
                int nj0 = njp * 2, nj1 = nj0 + 1;
                uint32_t bo0 = bbase + nj0 * (8 * ROWB) + ko;
                uint32_t bo1 = bbase + nj1 * (8 * ROWB) + ko;
                uint32_t bh[4], bl[4];
                bh[0] = lds32(bo0);
                bh[1] = lds32(bo0 + 16);
                bh[2] = lds32(bo1);
                bh[3] = lds32(bo1 + 16);
                bl[0] = lds32(bo0 + 10240);
                bl[1] = lds32(bo0 + 10240 + 16);
                bl[2] = lds32(bo1 + 10240);
                bl[3] = lds32(bo1 + 10240 + 16);
                // term-major across the pair: acc reuse distance 4
                mma16816(acc[0][nj0], ah[0], bh[0], bh[1]);
                mma16816(acc[1][nj0], ah[1], bh[0], bh[1]);
                mma16816(acc[0][nj1], ah[0], bh[2], bh[3]);
                mma16816(acc[1][nj1], ah[1], bh[2], bh[3]);
                mma16816(acc[0][nj0], ah[0], bl[0], bl[1]);
                mma16816(acc[1][nj0], ah[1], bl[0], bl[1]);
                mma16816(acc[0][nj1], ah[0], bl[2], bl[3]);
                mma16816(acc[1][nj1], ah[1], bl[2], bl[3]);
                mma16816(acc[0][nj0], al[0], bh[0], bh[1]);
                mma16816(acc[1][nj0], al[1], bh[0], bh[1]);
                mma16816(acc[0][nj1], al[0], bh[2], bh[3]);
                mma16816(acc[1][nj1], al[1], bh[2], bh[3]);
            }
        }
        __syncthreads();
    }

    float mnv = 0.f, mxv = 0.f;
    if (EPI == EP_XHAT_CLIP) {
        mnv = o2f(g_mm[0]);
        mxv = o2f(g_mm[1]);
    }
#pragma unroll
    for (int mi = 0; mi < 2; mi++)
#pragma unroll
        for (int nj = 0; nj < 8; nj++) {
            int row = m0 + wm * 32 + mi * 16 + q;
            int col = n0 + wn * 64 + nj * 8 + 2 * t;
            ep2<EPI>(make_float2(acc[mi][nj][0], acc[mi][nj][1]), row, col, N, C, x0p, dUp, up,
                     oh, ol, outp, mnv, mxv);
            ep2<EPI>(make_float2(acc[mi][nj][2], acc[mi][nj][3]), row + 8, col, N, C, x0p, dUp,
                     up, oh, ol, outp, mnv, mxv);
        }
}

extern "C" void kernel_launch(void* const* d_in, const int* in_sizes, int n_in,
                              void* d_out, int out_size) {
    const float* y = (const float*)d_in[0];
    const float* x = (const float*)d_in[1];
    const float* a = (const float*)d_in[2];
    const float* phi = (const float*)d_in[3];
    float* out = (float*)d_out;

    float *G, *linv, *dU, *x0, *u;
    __nv_bfloat16 *gTh, *gTl, *phih, *phil, *yh, *yl, *wh, *wl, *xhh, *xhl;
    cudaGetSymbolAddress((void**)&G, g_G);
    cudaGetSymbolAddress((void**)&linv, g_linv);
    cudaGetSymbolAddress((void**)&dU, g_dU);
    cudaGetSymbolAddress((void**)&x0, g_x0);
    cudaGetSymbolAddress((void**)&u, g_u);
    cudaGetSymbolAddress((void**)&gTh, g_gTh);
    cudaGetSymbolAddress((void**)&gTl, g_gTl);
    cudaGetSymbolAddress((void**)&phih, g_phih);
    cudaGetSymbolAddress((void**)&phil, g_phil);
    cudaGetSymbolAddress((void**)&yh, g_yh);
    cudaGetSymbolAddress((void**)&yl, g_yl);
    cudaGetSymbolAddress((void**)&wh, g_wh);
    cudaGetSymbolAddress((void**)&wl, g_wl);
    cudaGetSymbolAddress((void**)&xhh, g_xhh);
    cudaGetSymbolAddress((void**)&xhl, g_xhl);

    cudaFuncSetAttribute(tgemm_k<EP_G_STORE>, cudaFuncAttributeMaxDynamicSharedMemorySize, DSMEM_TOTAL);
    cudaFuncSetAttribute(tgemm_k<EP_X0>, cudaFuncAttributeMaxDynamicSharedMemorySize, DSMEM_TOTAL);
    cudaFuncSetAttribute(tgemm_k<EP_XHAT>, cudaFuncAttributeMaxDynamicSharedMemorySize, DSMEM_TOTAL);
    cudaFuncSetAttribute(tgemm_k<EP_XHAT_CLIP>, cudaFuncAttributeMaxDynamicSharedMemorySize, DSMEM_TOTAL);
    cudaFuncSetAttribute(tgemm_k<EP_ADMM>, cudaFuncAttributeMaxDynamicSharedMemorySize, DSMEM_TOTAL);
    cudaFuncSetAttribute(tgemm_k<EP_ADMM_U0>, cudaFuncAttributeMaxDynamicSharedMemorySize, DSMEM_TOTAL);

    dim3 blk(256);
    dim3 b32(32, 8);
    dim3 gG(AD / 128, AD / 128);   // (16,16)
    dim3 g1(AD / 128, BD / 128);   // (16,16)
    dim3 g2(SD / 128, BD / 128);   // (48,16)

    // pack gT = [aT | phiT] (A x KT), K-major
    tsplit_k<<<dim3(AD / 32, SD / 32), b32>>>(phi, SD, AD, KT, gTh + MD, gTl + MD);  // 0
    tsplit_k<<<dim3(AD / 32, MD / 32), b32>>>(a, MD, AD, KT, gTh, gTl);              // 1
    split_k<<<(SD * AD) / 256, 256>>>(phi, phih, phil, SD * AD);                     // 2
    // G = aT a + phiT phi in ONE K=6656 GEMM   (index 3 -> profiled)
    tgemm_k<EP_G_STORE><<<gG, blk, DSMEM_TOTAL>>>(gTh, gTl, KT, gTh, gTl, KT, KT, AD, G,
                                                  nullptr, nullptr, nullptr, nullptr, nullptr, nullptr);
    mm_init_k<<<1, 1>>>();
    mm_reduce_k<<<256, 256>>>(x, BD * AD);
    split_k<<<(BD * MD) / 256, 256>>>(y, yh, yl, BD * MD);

    for (int kb = 0; kb < AD / NB; kb++) {
        int k0 = kb * NB;
        chol_diag_k<<<1, 256>>>(G, linv, dU, k0);
        int nrem = AD - k0 - NB;
        if (nrem > 0) {
            panel_k<<<nrem / 32, 256>>>(G, linv, k0);
            dim3 gs((nrem + 127) / 128, (nrem + 127) / 128);
            float* Gp = G + (size_t)(k0 + NB) * AD + k0;
            float* Gc = G + (size_t)(k0 + NB) * AD + (k0 + NB);
            syrk_k<<<gs, blk>>>(Gp, Gc, nrem, AD);
        }
    }

    // x0 = y@a (B side = aT = gT cols [0,512)); also xh = dU*x0 (iter-1, w=0)
    tgemm_k<EP_X0><<<g1, blk, DSMEM_TOTAL>>>(yh, yl, MD, gTh, gTl, KT, MD, AD, x0,
                                             nullptr, dU, nullptr, xhh, xhl, nullptr);
    // iter 1 second half: u = 0
    tgemm_k<EP_ADMM_U0><<<g2, blk, DSMEM_TOTAL>>>(xhh, xhl, AD, phih, phil, AD, AD, SD, nullptr,
                                                  nullptr, nullptr, u, wh, wl, nullptr);
    for (int it = 2; it <= 9; it++) {
        tgemm_k<EP_XHAT><<<g1, blk, DSMEM_TOTAL>>>(wh, wl, SD, gTh + MD, gTl + MD, KT, SD, AD,
                                                   nullptr, x0, dU, nullptr, xhh, xhl, nullptr);
        tgemm_k<EP_ADMM><<<g2, blk, DSMEM_TOTAL>>>(xhh, xhl, AD, phih, phil, AD, AD, SD, nullptr,
                                                   nullptr, nullptr, u, wh, wl, nullptr);
    }
    tgemm_k<EP_XHAT_CLIP><<<g1, blk, DSMEM_TOTAL>>>(wh, wl, SD, gTh + MD, gTl + MD, KT, SD, AD,
                                                    nullptr, x0, dU, nullptr, nullptr, nullptr, out);
}

// round 16
// speedup vs baseline: 1.0406x; 1.0058x over previous
#include <cuda_runtime.h>
#include <cuda_bf16.h>
#include <cstdint>
#include <cstddef>

#define BD 2048
#define MD 512
#define AD 2048
#define SD 6144
#define KT 6656  // MD + SD, packed Gram K
#define NB 64
#define CHOL_P 296  // persistent Cholesky grid: 2 CTAs/SM, full machine

// smem stage layout: rows padded to 80B (32 bf16 + 16B pad) -> conflict-free lds
#define ROWB 80
#define OAL 10240
#define OBH 20480
#define OBL 30720
#define SSTG 40960
#define DSMEM_TOTAL (2 * SSTG)

__device__ float g_G[AD * AD];
__device__ float g_linv[NB * NB];
__device__ float g_dU[AD];
__device__ float g_x0[BD * AD];
__device__ float g_u[BD * SD];
__device__ unsigned g_mm[2];
__device__ unsigned g_sync;
__device__ __align__(16) __nv_bfloat16 g_gTh[AD * KT], g_gTl[AD * KT];  // [aT | phiT] K-major
__device__ __align__(16) __nv_bfloat16 g_phih[SD * AD], g_phil[SD * AD];
__device__ __align__(16) __nv_bfloat16 g_yh[BD * MD], g_yl[BD * MD];
__device__ __align__(16) __nv_bfloat16 g_wh[BD * SD], g_wl[BD * SD];
__device__ __align__(16) __nv_bfloat16 g_xhh[BD * AD], g_xhl[BD * AD];

__device__ __forceinline__ unsigned f2o(float f) {
    unsigned b = __float_as_uint(f);
    return (b & 0x80000000u) ? ~b : (b | 0x80000000u);
}
__device__ __forceinline__ float o2f(unsigned u) {
    unsigned b = (u & 0x80000000u) ? (u ^ 0x80000000u) : ~u;
    return __uint_as_float(b);
}
__device__ __forceinline__ void split_bf(float x, __nv_bfloat16& h, __nv_bfloat16& l) {
    __nv_bfloat16 hb = __float2bfloat16(x);
    h = hb;
    l = __float2bfloat16(x - __bfloat162float(hb));
}
__device__ __forceinline__ uint32_t s2u(const void* p) {
    uint32_t a;
    asm("{ .reg .u64 t; cvta.to.shared.u64 t, %1; cvt.u32.u64 %0, t; }" : "=r"(a) : "l"(p));
    return a;
}
__device__ __forceinline__ uint32_t lds32(uint32_t a) {
    uint32_t v;
    asm volatile("ld.shared.b32 %0, [%1];" : "=r"(v) : "r"(a));
    return v;
}
__device__ __forceinline__ void cp16(uint32_t d, const void* s) {
    asm volatile("cp.async.cg.shared.global [%0], [%1], 16;" ::"r"(d), "l"(s));
}
__device__ __forceinline__ void mma16816(float* c, const uint32_t* a, uint32_t b0, uint32_t b1) {
    asm volatile(
        "mma.sync.aligned.m16n8k16.row.col.f32.bf16.bf16.f32 "
        "{%0,%1,%2,%3}, {%4,%5,%6,%7}, {%8,%9}, {%0,%1,%2,%3};"
        : "+f"(c[0]), "+f"(c[1]), "+f"(c[2]), "+f"(c[3])
        : "r"(a[0]), "r"(a[1]), "r"(a[2]), "r"(a[3]), "r"(b0), "r"(b1));
}

__global__ void mm_init_k() {
    g_mm[0] = 0xFFFFFFFFu;
    g_mm[1] = 0u;
}
__global__ void zero_sync_k() { g_sync = 0u; }

__global__ void mm_reduce_k(const float* __restrict__ x, int n) {
    unsigned mn = 0xFFFFFFFFu, mx = 0u;
    for (int i = blockIdx.x * blockDim.x + threadIdx.x; i < n; i += gridDim.x * blockDim.x) {
        unsigned o = f2o(x[i]);
        mn = min(mn, o);
        mx = max(mx, o);
    }
    __shared__ unsigned smn[256], smx[256];
    smn[threadIdx.x] = mn;
    smx[threadIdx.x] = mx;
    __syncthreads();
    for (int s = 128; s > 0; s >>= 1) {
        if (threadIdx.x < s) {
            smn[threadIdx.x] = min(smn[threadIdx.x], smn[threadIdx.x + s]);
            smx[threadIdx.x] = max(smx[threadIdx.x], smx[threadIdx.x + s]);
        }
        __syncthreads();
    }
    if (threadIdx.x == 0) {
        atomicMin(&g_mm[0], smn[0]);
        atomicMax(&g_mm[1], smx[0]);
    }
}

__global__ void split_k(const float* __restrict__ s, __nv_bfloat16* __restrict__ h,
                        __nv_bfloat16* __restrict__ l, int n) {
    int i = blockIdx.x * 256 + threadIdx.x;
    if (i < n) {
        __nv_bfloat16 hh, ll;
        split_bf(s[i], hh, ll);
        h[i] = hh;
        l[i] = ll;
    }
}

// transposed split with output row-stride ld: out[c*ld + r] = split(src[r*Cc + c])
__global__ void tsplit_k(const float* __restrict__ src, int R, int Cc, int ld,
                         __nv_bfloat16* __restrict__ th, __nv_bfloat16* __restrict__ tl) {
    __shared__ float t[32][33];
    int bc = blockIdx.x * 32, br = blockIdx.y * 32;
    int x = threadIdx.x, y = threadIdx.y;
#pragma unroll
    for (int dy = 0; dy < 32; dy += 8) t[y + dy][x] = src[(size_t)(br + y + dy) * Cc + bc + x];
    __syncthreads();
#pragma unroll
    for (int dy = 0; dy < 32; dy += 8) {
        size_t o = (size_t)(bc + y + dy) * ld + br + x;
        __nv_bfloat16 h, l;
        split_bf(t[x][y + dy], h, l);
        th[o] = h;
        tl[o] = l;
    }
}

// ---------------- persistent fused Cholesky: 1 launch, 32 rounds, full-machine grid ----------
__global__ __launch_bounds__(256, 2) void chol_all_k(float* __restrict__ G,
                                                     float* __restrict__ linv,
                                                     float* __restrict__ dU) {
    __shared__ float pool[2 * NB * (NB + 1)];
    int tid = threadIdx.x;
    int bid = blockIdx.x;
    unsigned gen = 0;

#define GBAR()                                                           \
    do {                                                                 \
        __syncthreads();                                                 \
        if (tid == 0) {                                                  \
            __threadfence();                                             \
            atomicAdd(&g_sync, 1u);                                      \
            unsigned tgt = (++gen) * (unsigned)CHOL_P;                   \
            while (*((volatile unsigned*)&g_sync) < tgt) {}              \
            __threadfence();                                             \
        }                                                                \
        __syncthreads();                                                 \
    } while (0)

    for (int kb = 0; kb < AD / NB; kb++) {
        int k0 = kb * NB;
        int nrem = AD - k0 - NB;

        // ---- Phase A: diagonal block factor + inv(L11), block 0 only ----
        if (bid == 0) {
            float(*s)[NB + 1] = (float(*)[NB + 1])pool;
            float(*xs)[NB + 1] = (float(*)[NB + 1])(pool + NB * (NB + 1));
            int row = tid & 63, seg = tid >> 6;
#pragma unroll
            for (int j = 0; j < 16; j++) {
                int c = seg * 16 + j;
                s[row][c] = G[(size_t)(k0 + row) * AD + k0 + c];
            }
            __syncthreads();
            for (int j = 0; j < NB; j++) {
                float ajj = s[j][j];
                __syncthreads();
                float d = sqrtf(ajj);
                if (seg == 0 && row >= j) {
                    if (row == j) {
                        s[j][j] = d;
                        dU[k0 + j] = 1.0f / (d * d);
                    } else {
                        s[row][j] = s[row][j] / d;
                    }
                }
                __syncthreads();
                if (row > j) {
                    float lj = s[row][j];
                    for (int p = j + 1 + seg; p <= row; p += 4) s[row][p] -= lj * s[p][j];
                }
                __syncthreads();
            }
            if (seg == 0) {
                int c = row;
                for (int r = 0; r < c; r++) xs[r][c] = 0.0f;
                xs[c][c] = 1.0f / s[c][c];
                for (int r = c + 1; r < NB; r++) {
                    float acc = 0.0f;
                    for (int p = c; p < r; p++) acc += s[r][p] * xs[p][c];
                    xs[r][c] = -acc / s[r][r];
                }
            }
            __syncthreads();
            for (int i = tid; i < NB * NB; i += 256) linv[i] = xs[i >> 6][i & 63];
        }
        GBAR();

        // ---- Phase B: panel L21 = A21 * Linv^T (32-row slices) ----
        if (nrem > 0) {
            int npan = nrem / 32;
            for (int sl = bid; sl < npan; sl += CHOL_P) {
                float(*li)[NB + 1] = (float(*)[NB + 1])pool;
                float(*ar)[NB] = (float(*)[NB])(pool + NB * (NB + 1));
                for (int i = tid; i < NB * NB; i += 256) li[i >> 6][i & 63] = linv[i];
                int row0 = k0 + NB + sl * 32;
                for (int i = tid; i < 32 * NB; i += 256) {
                    int r = i >> 6, p = i & 63;
                    ar[r][p] = G[(size_t)(row0 + r) * AD + k0 + p];
                }
                __syncthreads();
                int j = tid & 63;
                for (int r = tid >> 6; r < 32; r += 4) {
                    float acc = 0.0f;
#pragma unroll
                    for (int p = 0; p < NB; p++) acc += ar[r][p] * li[j][p];
                    G[(size_t)(row0 + r) * AD + k0 + j] = acc;
                }
                __syncthreads();
            }
        }
        GBAR();

        // ---- Phase C: trailing update C -= P P^T (128x128 tiles) ----
        if (nrem > 0) {
            const float* Pp = G + (size_t)(k0 + NB) * AD + k0;
            float* Cc = G + (size_t)(k0 + NB) * AD + (k0 + NB);
            int nbx = (nrem + 127) / 128;
            float(*As)[128] = (float(*)[128])pool;
            float(*Bs)[128] = (float(*)[128])(pool + 16 * 128);
            for (int idx = bid; idx < nbx * nbx; idx += CHOL_P) {
                int bm0 = (idx / nbx) * 128, bn0 = (idx % nbx) * 128;
                int tx = tid & 15, ty = tid >> 4;
                float acc[8][8];
#pragma unroll
                for (int i = 0; i < 8; i++)
#pragma unroll
                    for (int j = 0; j < 8; j++) acc[i][j] = 0.0f;
                for (int kk = 0; kk < NB; kk += 16) {
#pragma unroll
                    for (int L = 0; L < 2; L++) {
                        int ii = tid + L * 256;
                        int r = ii >> 2, fk = (ii & 3) << 2;
                        float4 v = make_float4(0.f, 0.f, 0.f, 0.f);
                        if ((bm0 + r) < nrem)
                            v = *(const float4*)(Pp + (size_t)(bm0 + r) * AD + kk + fk);
                        As[fk + 0][r] = v.x;
                        As[fk + 1][r] = v.y;
                        As[fk + 2][r] = v.z;
                        As[fk + 3][r] = v.w;
                    }
#pragma unroll
                    for (int L = 0; L < 2; L++) {
                        int ii = tid + L * 256;
                        int r = ii >> 2, fk = (ii & 3) << 2;
                        float4 v = make_float4(0.f, 0.f, 0.f, 0.f);
                        if ((bn0 + r) < nrem)
                            v = *(const float4*)(Pp + (size_t)(bn0 + r) * AD + kk + fk);
                        Bs[fk + 0][r] = v.x;
                        Bs[fk + 1][r] = v.y;
                        Bs[fk + 2][r] = v.z;
                        Bs[fk + 3][r] = v.w;
                    }
                    __syncthreads();
#pragma unroll
                    for (int k = 0; k < 16; k++) {
                        float arf[8], brf[8];
#pragma unroll
                        for (int i = 0; i < 8; i++) arf[i] = As[k][ty * 8 + i];
#pragma unroll
                        for (int j = 0; j < 8; j++) brf[j] = Bs[k][tx * 8 + j];
#pragma unroll
                        for (int i = 0; i < 8; i++)
#pragma unroll
                            for (int j = 0; j < 8; j++) acc[i][j] += arf[i] * brf[j];
                    }
                    __syncthreads();
                }
#pragma unroll
                for (int i = 0; i < 8; i++) {
                    int row = bm0 + ty * 8 + i;
                    if (row >= nrem) continue;
#pragma unroll
                    for (int j = 0; j < 8; j++) {
                        int col = bn0 + tx * 8 + j;
                        if (col >= nrem) continue;
                        Cc[(size_t)row * AD + col] -= acc[i][j];
                    }
                }
            }
        }
        GBAR();
    }
#undef GBAR
}

// ---------------- warp-MMA bf16x3 GEMM (128x128 CTA, 2 CTAs/SM), fused epilogues --------
enum { EP_G_STORE = 0, EP_X0, EP_XHAT, EP_XHAT_CLIP, EP_ADMM, EP_ADMM_U0 };

template <int EPI>
__device__ __forceinline__ void ep2(float2 v, int row, int col, int N, float* C,
                                    const float* x0p, const float* dUp, float* up,
                                    __nv_bfloat16* oh, __nv_bfloat16* ol, float* outp,
                                    float mnv, float mxv) {
    size_t o = (size_t)row * N + col;
    if (EPI == EP_G_STORE) {
        *(float2*)(C + o) = v;
    } else if (EPI == EP_X0) {
        *(float2*)(C + o) = v;
        float2 d = *(const float2*)(dUp + col);
        __nv_bfloat162 hh, ll;
        split_bf(d.x * v.x, hh.x, ll.x);
        split_bf(d.y * v.y, hh.y, ll.y);
        *(__nv_bfloat162*)(oh + o) = hh;
        *(__nv_bfloat162*)(ol + o) = ll;
    } else if (EPI == EP_XHAT) {
        float2 x0v = *(const float2*)(x0p + o);
        float2 d = *(const float2*)(dUp + col);
        __nv_bfloat162 hh, ll;
        split_bf(d.x * (x0v.x + v.x), hh.x, ll.x);
        split_bf(d.y * (x0v.y + v.y), hh.y, ll.y);
        *(__nv_bfloat162*)(oh + o) = hh;
        *(__nv_bfloat162*)(ol + o) = ll;
    } else if (EPI == EP_XHAT_CLIP) {
        float2 x0v = *(const float2*)(x0p + o);
        float2 d = *(const float2*)(dUp + col);
        float2 t;
        t.x = fminf(fmaxf(d.x * (x0v.x + v.x), mnv), mxv);
        t.y = fminf(fmaxf(d.y * (x0v.y + v.y), mnv), mxv);
        *(float2*)(outp + o) = t;
    } else {
        float2 uo = make_float2(0.f, 0.f);
        if (EPI == EP_ADMM) uo = *(float2*)(up + o);
        __nv_bfloat162 hh, ll;
        float2 un;
#pragma unroll
        for (int e = 0; e < 2; e++) {
            float fxu = (e ? v.y : v.x) + (e ? uo.y : uo.x);
            float sa = fabsf(fxu) - 0.1f;  // LAMDA / RHO
            float z = sa > 0.0f ? copysignf(sa, fxu) : 0.0f;
            float u2 = (e ? uo.y : uo.x) + fxu - z;
            if (e) un.y = u2; else un.x = u2;
            __nv_bfloat16 h, l;
            split_bf(z - u2, h, l);
            if (e) { hh.y = h; ll.y = l; } else { hh.x = h; ll.x = l; }
        }
        *(float2*)(up + o) = un;
        *(__nv_bfloat162*)(oh + o) = hh;
        *(__nv_bfloat162*)(ol + o) = ll;
    }
}

template <int EPI>
__global__ __launch_bounds__(256, 2) void tgemm_k(
    const __nv_bfloat16* __restrict__ Ah, const __nv_bfloat16* __restrict__ Al, int lda,
    const __nv_bfloat16* __restrict__ Bh, const __nv_bfloat16* __restrict__ Bl, int ldb,
    int K, int N, float* __restrict__ C, const float* __restrict__ x0p,
    const float* __restrict__ dUp, float* __restrict__ up, __nv_bfloat16* __restrict__ oh,
    __nv_bfloat16* __restrict__ ol, float* __restrict__ outp) {
    extern __shared__ char ds[];
    uint32_t sb = s2u(ds);
    int tid = threadIdx.x, wid = tid >> 5, lane = tid & 31;
    int q = lane >> 2, t = lane & 3;
    int wm = wid >> 1, wn = wid & 1;
    int m0 = blockIdx.y * 128, n0 = blockIdx.x * 128;

    float acc[2][8][4];
#pragma unroll
    for (int mi = 0; mi < 2; mi++)
#pragma unroll
        for (int nj = 0; nj < 8; nj++)
#pragma unroll
            for (int e = 0; e < 4; e++) acc[mi][nj][e] = 0.0f;

    int lr = tid >> 2, lc = tid & 3;
    int nK = K / 32;

    {
        uint32_t st = sb;
        int gc = lc * 8;
#pragma unroll
        for (int i = 0; i < 2; i++) {
            int r = lr + i * 64;
            uint32_t dso = st + r * ROWB + lc * 16;
            cp16(dso, Ah + (size_t)(m0 + r) * lda + gc);
            cp16(dso + OAL, Al + (size_t)(m0 + r) * lda + gc);
            cp16(dso + OBH, Bh + (size_t)(n0 + r) * ldb + gc);
            cp16(dso + OBL, Bl + (size_t)(n0 + r) * ldb + gc);
        }
        asm volatile("cp.async.commit_group;" ::: "memory");
    }

    for (int kb = 0; kb < nK; kb++) {
        int buf = kb & 1;
        if (kb + 1 < nK) {
            uint32_t st = sb + (buf ^ 1) * SSTG;
            int gc = (kb + 1) * 32 + lc * 8;
#pragma unroll
            for (int i = 0; i < 2; i++) {
                int r = lr + i * 64;
                uint32_t dso = st + r * ROWB + lc * 16;
                cp16(dso, Ah + (size_t)(m0 + r) * lda + gc);
                cp16(dso + OAL, Al + (size_t)(m0 + r) * lda + gc);
                cp16(dso + OBH, Bh + (size_t)(n0 + r) * ldb + gc);
                cp16(dso + OBL, Bl + (size_t)(n0 + r) * ldb + gc);
            }
            asm volatile("cp.async.commit_group;" ::: "memory");
            asm volatile("cp.async.wait_group 1;" ::: "memory");
        } else {
            asm volatile("cp.async.wait_group 0;" ::: "memory");
        }
        __syncthreads();

        uint32_t st = sb + buf * SSTG;
        uint32_t abase = st + (wm * 32 + q) * ROWB + t * 4;
        uint32_t bbase = st + OBH + (wn * 64 + q) * ROWB + t * 4;
#pragma unroll
        for (int s = 0; s < 2; s++) {
            uint32_t ko = s * 32;
            uint32_t ah[2][4], al[2][4];
#pragma unroll
            for (int mi = 0; mi < 2; mi++) {
                uint32_t ro = abase + mi * (16 * ROWB) + ko;
                ah[mi][0] = lds32(ro);
                ah[mi][1] = lds32(ro + 8 * ROWB);
                ah[mi][2] = lds32(ro + 16);
                ah[mi][3] = lds32(ro + 8 * ROWB + 16);
                al[mi][0] = lds32(ro + OAL);
                al[mi][1] = lds32(ro + OAL + 8 * ROWB);
                al[mi][2] = lds32(ro + OAL + 16);
                al[mi][3] = lds32(ro + OAL + 8 * ROWB + 16);
            }
#pragma unroll
            for (int njp = 0; njp < 4; njp++) {
                int nj0 = njp * 2, nj1 = nj0 + 1;
                uint32_t bo0 = bbase + nj0 * (8 * ROWB) + ko;
                uint32_t bo1 = bbase + nj1 * (8 * ROWB) + ko;
                uint32_t bh[4], bl[4];
                bh[0] = lds32(bo0);
                bh[1] = lds32(bo0 + 16);
                bh[2] = lds32(bo1);
                bh[3] = lds32(bo1 + 16);
                bl[0] = lds32(bo0 + 10240);
                bl[1] = lds32(bo0 + 10240 + 16);
                bl[2] = lds32(bo1 + 10240);
                bl[3] = lds32(bo1 + 10240 + 16);
                mma16816(acc[0][nj0], ah[0], bh[0], bh[1]);
                mma16816(acc[1][nj0], ah[1], bh[0], bh[1]);
                mma16816(acc[0][nj1], ah[0], bh[2], bh[3]);
                mma16816(acc[1][nj1], ah[1], bh[2], bh[3]);
                mma16816(acc[0][nj0], ah[0], bl[0], bl[1]);
                mma16816(acc[1][nj0], ah[1], bl[0], bl[1]);
                mma16816(acc[0][nj1], ah[0], bl[2], bl[3]);
                mma16816(acc[1][nj1], ah[1], bl[2], bl[3]);
                mma16816(acc[0][nj0], al[0], bh[0], bh[1]);
                mma16816(acc[1][nj0], al[1], bh[0], bh[1]);
                mma16816(acc[0][nj1], al[0], bh[2], bh[3]);
                mma16816(acc[1][nj1], al[1], bh[2], bh[3]);
            }
        }
        __syncthreads();
    }

    float mnv = 0.f, mxv = 0.f;
    if (EPI == EP_XHAT_CLIP) {
        mnv = o2f(g_mm[0]);
        mxv = o2f(g_mm[1]);
    }
#pragma unroll
    for (int mi = 0; mi < 2; mi++)
#pragma unroll
        for (int nj = 0; nj < 8; nj++) {
            int row = m0 + wm * 32 + mi * 16 + q;
            int col = n0 + wn * 64 + nj * 8 + 2 * t;
            ep2<EPI>(make_float2(acc[mi][nj][0], acc[mi][nj][1]), row, col, N, C, x0p, dUp, up,
                     oh, ol, outp, mnv, mxv);
            ep2<EPI>(make_float2(acc[mi][nj][2], acc[mi][nj][3]), row + 8, col, N, C, x0p, dUp,
                     up, oh, ol, outp, mnv, mxv);
        }
}

extern "C" void kernel_launch(void* const* d_in, const int* in_sizes, int n_in,
                              void* d_out, int out_size) {
    const float* y = (const float*)d_in[0];
    const float* x = (const float*)d_in[1];
    const float* a = (const float*)d_in[2];
    const float* phi = (const float*)d_in[3];
    float* out = (float*)d_out;

    float *G, *linv, *dU, *x0, *u;
    __nv_bfloat16 *gTh, *gTl, *phih, *phil, *yh, *yl, *wh, *wl, *xhh, *xhl;
    cudaGetSymbolAddress((void**)&G, g_G);
    cudaGetSymbolAddress((void**)&linv, g_linv);
    cudaGetSymbolAddress((void**)&dU, g_dU);
    cudaGetSymbolAddress((void**)&x0, g_x0);
    cudaGetSymbolAddress((void**)&u, g_u);
    cudaGetSymbolAddress((void**)&gTh, g_gTh);
    cudaGetSymbolAddress((void**)&gTl, g_gTl);
    cudaGetSymbolAddress((void**)&phih, g_phih);
    cudaGetSymbolAddress((void**)&phil, g_phil);
    cudaGetSymbolAddress((void**)&yh, g_yh);
    cudaGetSymbolAddress((void**)&yl, g_yl);
    cudaGetSymbolAddress((void**)&wh, g_wh);
    cudaGetSymbolAddress((void**)&wl, g_wl);
    cudaGetSymbolAddress((void**)&xhh, g_xhh);
    cudaGetSymbolAddress((void**)&xhl, g_xhl);

    cudaFuncSetAttribute(tgemm_k<EP_G_STORE>, cudaFuncAttributeMaxDynamicSharedMemorySize, DSMEM_TOTAL);
    cudaFuncSetAttribute(tgemm_k<EP_X0>, cudaFuncAttributeMaxDynamicSharedMemorySize, DSMEM_TOTAL);
    cudaFuncSetAttribute(tgemm_k<EP_XHAT>, cudaFuncAttributeMaxDynamicSharedMemorySize, DSMEM_TOTAL);
    cudaFuncSetAttribute(tgemm_k<EP_XHAT_CLIP>, cudaFuncAttributeMaxDynamicSharedMemorySize, DSMEM_TOTAL);
    cudaFuncSetAttribute(tgemm_k<EP_ADMM>, cudaFuncAttributeMaxDynamicSharedMemorySize, DSMEM_TOTAL);
    cudaFuncSetAttribute(tgemm_k<EP_ADMM_U0>, cudaFuncAttributeMaxDynamicSharedMemorySize, DSMEM_TOTAL);

    dim3 blk(256);
    dim3 b32(32, 8);
    dim3 gG(AD / 128, AD / 128);   // (16,16)
    dim3 g1(AD / 128, BD / 128);   // (16,16)
    dim3 g2(SD / 128, BD / 128);   // (48,16)

    // pack gT = [aT | phiT] (A x KT), K-major
    tsplit_k<<<dim3(AD / 32, SD / 32), b32>>>(phi, SD, AD, KT, gTh + MD, gTl + MD);  // 0
    tsplit_k<<<dim3(AD / 32, MD / 32), b32>>>(a, MD, AD, KT, gTh, gTl);              // 1
    split_k<<<(SD * AD) / 256, 256>>>(phi, phih, phil, SD * AD);                     // 2
    // G = aT a + phiT phi in ONE K=6656 GEMM   (index 3 -> profiled)
    tgemm_k<EP_G_STORE><<<gG, blk, DSMEM_TOTAL>>>(gTh, gTl, KT, gTh, gTl, KT, KT, AD, G,
                                                  nullptr, nullptr, nullptr, nullptr, nullptr, nullptr);
    mm_init_k<<<1, 1>>>();
    mm_reduce_k<<<256, 256>>>(x, BD * AD);
    split_k<<<(BD * MD) / 256, 256>>>(y, yh, yl, BD * MD);

    // fused persistent Cholesky (1 launch, full-machine grid)
    zero_sync_k<<<1, 1>>>();
    chol_all_k<<<CHOL_P, 256>>>(G, linv, dU);

    // x0 = y@a (B side = aT = gT cols [0,512)); also xh = dU*x0 (iter-1, w=0)
    tgemm_k<EP_X0><<<g1, blk, DSMEM_TOTAL>>>(yh, yl, MD, gTh, gTl, KT, MD, AD, x0,
                                             nullptr, dU, nullptr, xhh, xhl, nullptr);
    // iter 1 second half: u = 0
    tgemm_k<EP_ADMM_U0><<<g2, blk, DSMEM_TOTAL>>>(xhh, xhl, AD, phih, phil, AD, AD, SD, nullptr,
                                                  nullptr, nullptr, u, wh, wl, nullptr);
    for (int it = 2; it <= 9; it++) {
        tgemm_k<EP_XHAT><<<g1, blk, DSMEM_TOTAL>>>(wh, wl, SD, gTh + MD, gTl + MD, KT, SD, AD,
                                                   nullptr, x0, dU, nullptr, xhh, xhl, nullptr);
        tgemm_k<EP_ADMM><<<g2, blk, DSMEM_TOTAL>>>(xhh, xhl, AD, phih, phil, AD, AD, SD, nullptr,
                                                   nullptr, nullptr, u, wh, wl, nullptr);
    }
    tgemm_k<EP_XHAT_CLIP><<<g1, blk, DSMEM_TOTAL>>>(wh, wl, SD, gTh + MD, gTl + MD, KT, SD, AD,
                                                    nullptr, x0, dU, nullptr, nullptr, nullptr, out);
}